// round 8
// baseline (speedup 1.0000x reference)
#include <cuda_runtime.h>
#include <cuda_bf16.h>
#include <cstdint>

typedef unsigned int u32;
typedef unsigned long long u64;

#define C_IN   64
#define C_OUT  128
#define KK     27
#define HH     100000
#define TILE_H 128
#define NBLK   ((HH + TILE_H - 1) / TILE_H)
#define NTHR   512

// quantization: X in [-16256, 16256], digits d1 in [-127,127], d2 in [-64,64]
#define QRANGE 16256.0f

// smem: rows of 128 B ([digit1 64B | digit2 64B]), SW128 XOR swizzle
#define ST_A   0
#define ST_B   16384
#define STAGE  32768
#define NSTAGE 3
#define TILES_OFF 14336            // after sIdx (13824 B)
#define SMEM_BYTES (TILES_OFF + NSTAGE * STAGE)   // 112640

#define SWZ(o) ((o) ^ (((o) >> 3) & 0x70))

// ---------------- device scratch ----------------
__device__ signed char g_xq[(size_t)HH * 128];       // [h][d1 x64 | d2 x64]
__device__ signed char g_wq[KK * C_OUT * 128];       // [k][o][e1 x64 | e2 x64]
__device__ int g_is64;
__device__ int g_maxx, g_maxw;                       // float bits of max|.|

// ---------------- helpers ----------------
__device__ __forceinline__ u32 smem_u32(const void* p) {
    u32 a;
    asm("{ .reg .u64 t; cvta.to.shared.u64 t, %1; cvt.u32.u64 %0, t; }" : "=r"(a) : "l"(p));
    return a;
}
__device__ __forceinline__ void ldsm4(u32* r, u32 addr) {
    asm volatile("ldmatrix.sync.aligned.m8n8.x4.shared.b16 {%0,%1,%2,%3}, [%4];"
                 : "=r"(r[0]), "=r"(r[1]), "=r"(r[2]), "=r"(r[3]) : "r"(addr));
}
__device__ __forceinline__ void mmai8(int* d, const u32* a, const u32* b) {
    asm volatile("mma.sync.aligned.m16n8k32.row.col.s32.s8.s8.s32 "
                 "{%0,%1,%2,%3}, {%4,%5,%6,%7}, {%8,%9}, {%0,%1,%2,%3};"
                 : "+r"(d[0]), "+r"(d[1]), "+r"(d[2]), "+r"(d[3])
                 : "r"(a[0]), "r"(a[1]), "r"(a[2]), "r"(a[3]), "r"(b[0]), "r"(b[1]));
}
#define CP16(dst, src) \
    asm volatile("cp.async.cg.shared.global [%0], [%1], 16;" ::"r"(dst), "l"(src) : "memory")
#define CP16Z(dst, src, sz) \
    asm volatile("cp.async.cg.shared.global [%0], [%1], 16, %2;" ::"r"(dst), "l"(src), "r"(sz) : "memory")
#define CP_COMMIT() asm volatile("cp.async.commit_group;" ::: "memory")
#define CP_WAIT1()  asm volatile("cp.async.wait_group 1;" ::: "memory")

// quantize v*s -> two balanced digits
__device__ __forceinline__ void qsplit(float v, float s, signed char& hi, signed char& lo) {
    int X = __float2int_rn(v * s);
    int d1 = (X + 64) >> 7;          // round-half-up
    int d2 = X - (d1 << 7);          // in [-64, 63]
    hi = (signed char)d1;
    lo = (signed char)d2;
}

// ---------------- prep kernels ----------------
__global__ void detect_and_reset(const long long* __restrict__ n64) {
    if (threadIdx.x == 0) {
        int ok = 1;
        for (int i = 0; i < 256; i++) {
            long long v = n64[i];
            if (v < -(long long)HH || v >= (long long)HH) { ok = 0; break; }
        }
        g_is64 = ok;
        g_maxx = 0;
        g_maxw = 0;
    }
}

__global__ void max_x(const float* __restrict__ x) {
    float m = 0.f;
    for (size_t i = blockIdx.x * blockDim.x + threadIdx.x; i < (size_t)C_IN * HH;
         i += (size_t)gridDim.x * blockDim.x)
        m = fmaxf(m, fabsf(x[i]));
    // warp + block reduce, then one atomic
    for (int o = 16; o > 0; o >>= 1) m = fmaxf(m, __shfl_xor_sync(~0u, m, o));
    __shared__ float wm[32];
    if ((threadIdx.x & 31) == 0) wm[threadIdx.x >> 5] = m;
    __syncthreads();
    if (threadIdx.x < 32) {
        m = (threadIdx.x < (blockDim.x >> 5)) ? wm[threadIdx.x] : 0.f;
        for (int o = 16; o > 0; o >>= 1) m = fmaxf(m, __shfl_xor_sync(~0u, m, o));
        if (threadIdx.x == 0) atomicMax(&g_maxx, __float_as_int(m));
    }
}

__global__ void max_w(const float* __restrict__ w) {
    float m = 0.f;
    for (int i = blockIdx.x * blockDim.x + threadIdx.x; i < C_OUT * C_IN * KK;
         i += gridDim.x * blockDim.x)
        m = fmaxf(m, fabsf(w[i]));
    for (int o = 16; o > 0; o >>= 1) m = fmaxf(m, __shfl_xor_sync(~0u, m, o));
    __shared__ float wm[32];
    if ((threadIdx.x & 31) == 0) wm[threadIdx.x >> 5] = m;
    __syncthreads();
    if (threadIdx.x < 32) {
        m = (threadIdx.x < (blockDim.x >> 5)) ? wm[threadIdx.x] : 0.f;
        for (int o = 16; o > 0; o >>= 1) m = fmaxf(m, __shfl_xor_sync(~0u, m, o));
        if (threadIdx.x == 0) atomicMax(&g_maxw, __float_as_int(m));
    }
}

// x[c*HH + h] -> g_xq[h*128 + {c | 64+c}]  (transpose + quantize)
__global__ void split_x(const float* __restrict__ x) {
    __shared__ float tile[32][33];
    const float Rx = __int_as_float(g_maxx);
    const float s = (Rx > 0.f) ? (QRANGE / Rx) : 0.f;
    const int hb = blockIdx.x * 32, cb = blockIdx.y * 32;
    const int tx = threadIdx.x, ty = threadIdx.y;
#pragma unroll
    for (int i = 0; i < 32; i += 8) {
        int h = hb + tx;
        tile[ty + i][tx] = (h < HH) ? x[(size_t)(cb + ty + i) * HH + h] : 0.f;
    }
    __syncthreads();
#pragma unroll
    for (int i = 0; i < 32; i += 8) {
        int h = hb + ty + i, c = cb + tx;
        if (h < HH) {
            signed char hi, lo;
            qsplit(tile[tx][ty + i], s, hi, lo);
            g_xq[(size_t)h * 128 + c]      = hi;
            g_xq[(size_t)h * 128 + 64 + c] = lo;
        }
    }
}

// w[o*1728 + c*27 + k] -> g_wq[k*16384 + o*128 + {c | 64+c}]
__global__ void split_w(const float* __restrict__ w) {
    const float Rw = __int_as_float(g_maxw);
    const float s = (Rw > 0.f) ? (QRANGE / Rw) : 0.f;
    int idx = blockIdx.x * blockDim.x + threadIdx.x;
    if (idx >= KK * C_OUT * C_IN) return;
    int k = idx / (C_OUT * C_IN);
    int rem = idx % (C_OUT * C_IN);
    int o = rem / C_IN, c = rem % C_IN;
    signed char hi, lo;
    qsplit(w[(size_t)o * (C_IN * KK) + c * KK + k], s, hi, lo);
    g_wq[(size_t)k * 16384 + o * 128 + c]      = hi;
    g_wq[(size_t)k * 16384 + o * 128 + 64 + c] = lo;
}

// ---------------- main kernel ----------------
__global__ __launch_bounds__(NTHR, 1)
void conv_mma(const void* __restrict__ neigh_raw, float* __restrict__ out) {
    extern __shared__ char smem[];
    const u32 sbase = smem_u32(smem);
    int* sIdx = (int*)smem;
    const u32 tiles = sbase + TILES_OFF;

    const int tid = threadIdx.x;
    const int lid = tid & 31, wid = tid >> 5;    // 16 warps
    const int wr = wid & 3, wc = wid >> 2;       // warp grid 4(h) x 4(o)
    const int hb = blockIdx.x * TILE_H;

    // ---- stage neighbor indices ----
    {
        const int is64 = g_is64;
        const long long* n64 = (const long long*)neigh_raw;
        const int* n32 = (const int*)neigh_raw;
        for (int j = tid; j < TILE_H * KK; j += NTHR) {
            int hl = j / KK;
            int n = -1;
            if (hb + hl < HH) {
                size_t gi = (size_t)(hb + hl) * KK + (j % KK);
                long long v = is64 ? n64[gi] : (long long)n32[gi];
                if (v >= 0 && v < HH) n = (int)v;
            }
            sIdx[j] = n;
        }
    }
    __syncthreads();

    // ---- per-thread load roles: A = 4 threads per row, 2 x 16B each ----
    const int ar   = tid >> 2;                 // 0..127
    const int jsub = (tid & 3) * 2;            // 16B chunk pair

    // ---- ldmatrix address precompute ----
    const u32 a_ro = (u32)(lid & 15);
    const u32 a_co = (u32)(lid >> 4);
    const u32 b_ro = (u32)((lid & 7) + ((lid >> 4) << 3));
    const u32 b_co = (u32)((lid >> 3) & 1);
    const u32 a_row = (u32)(wr * 32) + a_ro;
    const u32 b_row = (u32)(wc * 32) + b_ro;
    const u32 axor = (a_row & 7) * 16;
    const u32 bxor = (b_row & 7) * 16;
    const u32 arow0 = a_row * 128, arow1 = (a_row + 16) * 128;
    const u32 brow0 = b_row * 128, brow1 = (b_row + 16) * 128;
    u32 koffA[4], koffB[4];
#pragma unroll
    for (int c4 = 0; c4 < 4; c4++) {
        koffA[c4] = ((u32)(c4 * 32) + a_co * 16) ^ axor;
        koffB[c4] = ((u32)(c4 * 32) + b_co * 16) ^ bxor;
    }

    int accP[2][4][4], accM[2][4][4];
#pragma unroll
    for (int mf = 0; mf < 2; mf++)
#pragma unroll
        for (int nf = 0; nf < 4; nf++)
#pragma unroll
            for (int r = 0; r < 4; r++) { accP[mf][nf][r] = 0; accM[mf][nf][r] = 0; }

    // ---- async load issuer for tap k into stage stg ----
    auto issue = [&](int k, int stg) {
        const u32 st = tiles + stg * STAGE;
        // A: gather row (128 B = [d1|d2]), this thread does 2 x 16B
        int n = sIdx[ar * KK + k];
        const char* src = (const char*)g_xq + ((n < 0 ? 0 : (size_t)n) * 128) + jsub * 16;
        u32 sz = (n < 0) ? 0u : 16u;
        u32 rowoff = (u32)ar * 128 + (u32)jsub * 16;
        CP16Z(st + ST_A + SWZ(rowoff),      src,      sz);
        CP16Z(st + ST_A + SWZ(rowoff + 16), src + 16, sz);
        // B: weights, 1024 x 16B chunks, 2 per thread
        const char* bs = (const char*)g_wq + (size_t)k * 16384;
#pragma unroll
        for (int i = 0; i < 2; i++) {
            int cc = tid + i * NTHR;
            CP16(st + ST_B + SWZ((u32)cc * 16), bs + cc * 16);
        }
    };

    issue(0, 0); CP_COMMIT();
    issue(1, 1); CP_COMMIT();

    u32 a[2][4], bt[2][4], b0[2][4], b1[2][4];

    int stg = 0, stgW = 2;
    for (int k = 0; k < KK; k++) {
        CP_WAIT1();
        __syncthreads();

        if (k + 2 < KK) issue(k + 2, stgW);
        CP_COMMIT();

        const u32 stA = tiles + stg * STAGE + ST_A;
        const u32 stB = tiles + stg * STAGE + ST_B;

        // resident B chunks 0,1 (e1 halves)
        ldsm4(b0[0], stB + brow0 + koffB[0]);
        ldsm4(b0[1], stB + brow1 + koffB[0]);
        ldsm4(b1[0], stB + brow0 + koffB[1]);
        ldsm4(b1[1], stB + brow1 + koffB[1]);

        // ---- chunk schedule: P11 (d1*e1) and Pmid (d1*e2 + d2*e1) ----
        // A c0 (d1 k0..31)
        ldsm4(a[0], stA + arow0 + koffA[0]);
        ldsm4(a[1], stA + arow1 + koffA[0]);
#pragma unroll
        for (int mf = 0; mf < 2; mf++)
#pragma unroll
            for (int g = 0; g < 2; g++) {
                mmai8(accP[mf][2 * g],     a[mf], &b0[g][0]);
                mmai8(accP[mf][2 * g + 1], a[mf], &b0[g][2]);
            }
        ldsm4(bt[0], stB + brow0 + koffB[2]);      // B c2 (e2 k0..31)
        ldsm4(bt[1], stB + brow1 + koffB[2]);
#pragma unroll
        for (int mf = 0; mf < 2; mf++)
#pragma unroll
            for (int g = 0; g < 2; g++) {
                mmai8(accM[mf][2 * g],     a[mf], &bt[g][0]);
                mmai8(accM[mf][2 * g + 1], a[mf], &bt[g][2]);
            }
        // A c1 (d1 k32..63)
        ldsm4(a[0], stA + arow0 + koffA[1]);
        ldsm4(a[1], stA + arow1 + koffA[1]);
#pragma unroll
        for (int mf = 0; mf < 2; mf++)
#pragma unroll
            for (int g = 0; g < 2; g++) {
                mmai8(accP[mf][2 * g],     a[mf], &b1[g][0]);
                mmai8(accP[mf][2 * g + 1], a[mf], &b1[g][2]);
            }
        ldsm4(bt[0], stB + brow0 + koffB[3]);      // B c3 (e2 k32..63)
        ldsm4(bt[1], stB + brow1 + koffB[3]);
#pragma unroll
        for (int mf = 0; mf < 2; mf++)
#pragma unroll
            for (int g = 0; g < 2; g++) {
                mmai8(accM[mf][2 * g],     a[mf], &bt[g][0]);
                mmai8(accM[mf][2 * g + 1], a[mf], &bt[g][2]);
            }
        // A c2 (d2 k0..31) x B c0 (e1)
        ldsm4(a[0], stA + arow0 + koffA[2]);
        ldsm4(a[1], stA + arow1 + koffA[2]);
#pragma unroll
        for (int mf = 0; mf < 2; mf++)
#pragma unroll
            for (int g = 0; g < 2; g++) {
                mmai8(accM[mf][2 * g],     a[mf], &b0[g][0]);
                mmai8(accM[mf][2 * g + 1], a[mf], &b0[g][2]);
            }
        // A c3 (d2 k32..63) x B c1 (e1)
        ldsm4(a[0], stA + arow0 + koffA[3]);
        ldsm4(a[1], stA + arow1 + koffA[3]);
#pragma unroll
        for (int mf = 0; mf < 2; mf++)
#pragma unroll
            for (int g = 0; g < 2; g++) {
                mmai8(accM[mf][2 * g],     a[mf], &b1[g][0]);
                mmai8(accM[mf][2 * g + 1], a[mf], &b1[g][2]);
            }

        stg  = (stg == NSTAGE - 1) ? 0 : stg + 1;
        stgW = (stgW == NSTAGE - 1) ? 0 : stgW + 1;
    }

    __syncthreads();
    // ---- epilogue: combine digits, relu, stage via smem, coalesced stores ----
    const float Rx = __int_as_float(g_maxx);
    const float Rw = __int_as_float(g_maxw);
    const float scale = (Rx / QRANGE) * (Rw / QRANGE);

    float* sC = (float*)(smem + TILES_OFF);
#pragma unroll
    for (int mf = 0; mf < 2; mf++)
#pragma unroll
        for (int nf = 0; nf < 4; nf++)
#pragma unroll
            for (int r = 0; r < 4; r++) {
                float v = ((float)accP[mf][nf][r] * 16384.f +
                           (float)accM[mf][nf][r] * 128.f) * scale;
                int m = wr * 32 + mf * 16 + (lid >> 2) + ((r >> 1) << 3);
                int n = wc * 32 + nf * 8 + ((lid & 3) << 1) + (r & 1);
                sC[n * 132 + m] = fmaxf(v, 0.f);
            }
    __syncthreads();
#pragma unroll
    for (int it = 0; it < 8; it++) {
        int idx = it * NTHR + tid;
        int o = idx >> 5, hq = idx & 31;
        int h = hb + hq * 4;
        if (h < HH) {
            float4 v = *(const float4*)(sC + o * 132 + hq * 4);
            *(float4*)(out + (size_t)o * HH + h) = v;
        }
    }
}

// ---------------- launch ----------------
extern "C" void kernel_launch(void* const* d_in, const int* in_sizes, int n_in,
                              void* d_out, int out_size) {
    const float* x = (const float*)d_in[0];
    const void* neigh = d_in[1];
    const float* w = (const float*)d_in[2];
    float* out = (float*)d_out;

    cudaFuncSetAttribute(conv_mma, cudaFuncAttributeMaxDynamicSharedMemorySize, SMEM_BYTES);

    detect_and_reset<<<1, 32>>>((const long long*)neigh);
    max_x<<<256, 256>>>(x);
    max_w<<<32, 256>>>(w);
    split_x<<<dim3((HH + 31) / 32, C_IN / 32), dim3(32, 8)>>>(x);
    split_w<<<(KK * C_OUT * C_IN + 255) / 256, 256>>>(w);
    conv_mma<<<NBLK, NTHR, SMEM_BYTES>>>(neigh, out);
}

// round 9
// speedup vs baseline: 2.4409x; 2.4409x over previous
#include <cuda_runtime.h>
#include <cuda_fp16.h>
#include <cstdint>

typedef unsigned int u32;
typedef unsigned long long u64;

#define C_IN   64
#define C_OUT  128
#define KK     27
#define HH     100000
#define TILE_H 128
#define NBLK   ((HH + TILE_H - 1) / TILE_H)
#define NTHR   512

// smem: 128B rows + SW128 XOR swizzle (conflict-free ldmatrix)
#define TILEB  16384               // 128 rows x 128 B
#define ST_AH  0
#define ST_AL  TILEB
#define ST_BH  (2 * TILEB)
#define ST_BL  (3 * TILEB)
#define STAGE  (4 * TILEB)         // 65536
#define NSTAGE 3
#define TILES_OFF 14336            // after sIdx (13824 B)
#define SMEM_BYTES (TILES_OFF + NSTAGE * STAGE)   // 210944

#define SWZ(o) ((o) ^ (((o) >> 3) & 0x70))

// ---------------- device scratch ----------------
__device__ __half g_xh[(size_t)HH * C_IN];
__device__ __half g_xl[(size_t)HH * C_IN];
__device__ __half g_wh[KK * C_OUT * C_IN];   // [k][o][c]
__device__ __half g_wl[KK * C_OUT * C_IN];
__device__ int g_is64;

// ---------------- helpers ----------------
__device__ __forceinline__ u32 smem_u32(const void* p) {
    u32 a;
    asm("{ .reg .u64 t; cvta.to.shared.u64 t, %1; cvt.u32.u64 %0, t; }" : "=r"(a) : "l"(p));
    return a;
}
__device__ __forceinline__ void ldsm4(u32* r, u32 addr) {
    asm volatile("ldmatrix.sync.aligned.m8n8.x4.shared.b16 {%0,%1,%2,%3}, [%4];"
                 : "=r"(r[0]), "=r"(r[1]), "=r"(r[2]), "=r"(r[3]) : "r"(addr));
}
// fp16 inputs, f32 accumulate (main term)
__device__ __forceinline__ void mma_f32(float* d, const u32* a, const u32* b) {
    asm volatile("mma.sync.aligned.m16n8k16.row.col.f32.f16.f16.f32 "
                 "{%0,%1,%2,%3}, {%4,%5,%6,%7}, {%8,%9}, {%0,%1,%2,%3};"
                 : "+f"(d[0]), "+f"(d[1]), "+f"(d[2]), "+f"(d[3])
                 : "r"(a[0]), "r"(a[1]), "r"(a[2]), "r"(a[3]), "r"(b[0]), "r"(b[1]));
}
// fp16 inputs, f16 accumulate (correction terms)
__device__ __forceinline__ void mma_f16(u32* d, const u32* a, const u32* b) {
    asm volatile("mma.sync.aligned.m16n8k16.row.col.f16.f16.f16.f16 "
                 "{%0,%1}, {%2,%3,%4,%5}, {%6,%7}, {%0,%1};"
                 : "+r"(d[0]), "+r"(d[1])
                 : "r"(a[0]), "r"(a[1]), "r"(a[2]), "r"(a[3]), "r"(b[0]), "r"(b[1]));
}
#define CP16(dst, src) \
    asm volatile("cp.async.cg.shared.global [%0], [%1], 16;" ::"r"(dst), "l"(src) : "memory")
#define CP16Z(dst, src, sz) \
    asm volatile("cp.async.cg.shared.global [%0], [%1], 16, %2;" ::"r"(dst), "l"(src), "r"(sz) : "memory")
#define CP_COMMIT() asm volatile("cp.async.commit_group;" ::: "memory")
#define CP_WAIT2()  asm volatile("cp.async.wait_group 2;" ::: "memory")

// ---------------- prep kernels ----------------
__global__ void detect_dtype(const long long* __restrict__ n64) {
    if (threadIdx.x == 0 && blockIdx.x == 0) {
        int ok = 1;
        for (int i = 0; i < 256; i++) {
            long long v = n64[i];
            if (v < -(long long)HH || v >= (long long)HH) { ok = 0; break; }
        }
        g_is64 = ok;
    }
}

__global__ void split_x(const float* __restrict__ x) {
    __shared__ float tile[32][33];
    const int hb = blockIdx.x * 32, cb = blockIdx.y * 32;
    const int tx = threadIdx.x, ty = threadIdx.y;
#pragma unroll
    for (int i = 0; i < 32; i += 8) {
        int h = hb + tx;
        tile[ty + i][tx] = (h < HH) ? x[(size_t)(cb + ty + i) * HH + h] : 0.f;
    }
    __syncthreads();
#pragma unroll
    for (int i = 0; i < 32; i += 8) {
        int h = hb + ty + i, c = cb + tx;
        if (h < HH) {
            float v = tile[tx][ty + i];
            __half hi = __float2half(v);
            float r = v - __half2float(hi);
            g_xh[(size_t)h * C_IN + c] = hi;
            g_xl[(size_t)h * C_IN + c] = __float2half(r);
        }
    }
}

__global__ void split_w(const float* __restrict__ w) {
    int idx = blockIdx.x * blockDim.x + threadIdx.x;
    if (idx >= KK * C_OUT * C_IN) return;
    int k = idx / (C_OUT * C_IN);
    int rem = idx % (C_OUT * C_IN);
    int o = rem / C_IN, c = rem % C_IN;
    float v = w[(size_t)o * (C_IN * KK) + c * KK + k];
    __half hi = __float2half(v);
    float r = v - __half2float(hi);
    g_wh[idx] = hi;
    g_wl[idx] = __float2half(r);
}

// ---------------- main kernel ----------------
__global__ __launch_bounds__(NTHR, 1)
void conv_mma(const void* __restrict__ neigh_raw, float* __restrict__ out) {
    extern __shared__ char smem[];
    const u32 sbase = smem_u32(smem);
    int* sIdx = (int*)smem;
    const u32 tiles = sbase + TILES_OFF;

    const int tid = threadIdx.x;
    const int lid = tid & 31, wid = tid >> 5;    // 16 warps
    const int wr = wid & 3, wc = wid >> 2;       // warp grid 4(h) x 4(o)
    const int hb = blockIdx.x * TILE_H;

    // ---- stage neighbor indices ----
    {
        const int is64 = g_is64;
        const long long* n64 = (const long long*)neigh_raw;
        const int* n32 = (const int*)neigh_raw;
        for (int j = tid; j < TILE_H * KK; j += NTHR) {
            int hl = j / KK;
            int n = -1;
            if (hb + hl < HH) {
                size_t gi = (size_t)(hb + hl) * KK + (j % KK);
                long long v = is64 ? n64[gi] : (long long)n32[gi];
                if (v >= 0 && v < HH) n = (int)v;
            }
            sIdx[j] = n;
        }
    }
    __syncthreads();

    // ---- per-thread load roles: A = (row, half, 4-chunk group) ----
    const int ar   = tid >> 2;                 // 0..127
    const int asel = (tid >> 1) & 1;           // 0 = hi, 1 = lo
    const int jgrp = (tid & 1) * 4;            // chunk group 0..3 / 4..7
    const __half* axsrc = asel ? g_xl : g_xh;
    const u32 atile = asel ? ST_AL : ST_AH;

    // ---- ldmatrix lane address components ----
    const u32 a_ro = (u32)(lid & 15);
    const u32 a_co = (u32)(lid >> 4);
    const u32 b_ro = (u32)((lid & 7) + ((lid >> 4) << 3));
    const u32 b_co = (u32)((lid >> 3) & 1);
    const u32 a_row = (u32)(wr * 32) + a_ro;
    const u32 b_row = (u32)(wc * 32) + b_ro;

    float accM[2][4][4];           // main term, f32
    u32   accC[2][4][2];           // corrections, f16x2 pairs
#pragma unroll
    for (int mf = 0; mf < 2; mf++)
#pragma unroll
        for (int nf = 0; nf < 4; nf++) {
#pragma unroll
            for (int r = 0; r < 4; r++) accM[mf][nf][r] = 0.f;
            accC[mf][nf][0] = 0u; accC[mf][nf][1] = 0u;
        }

    // ---- async load issuer for tap k into stage stg ----
    auto issue = [&](int k, int stg) {
        const u32 st = tiles + stg * STAGE;
        int n = sIdx[ar * KK + k];
        const char* src = (const char*)(axsrc + (n < 0 ? 0 : (size_t)n * C_IN)) + jgrp * 16;
        u32 sz = (n < 0) ? 0u : 16u;
        u32 rowoff = (u32)ar * 128 + (u32)jgrp * 16;
#pragma unroll
        for (int j = 0; j < 4; j++)
            CP16Z(st + atile + SWZ(rowoff + j * 16), src + j * 16, sz);
        const char* bhs = (const char*)(g_wh + (size_t)k * (C_OUT * C_IN));
        const char* bls = (const char*)(g_wl + (size_t)k * (C_OUT * C_IN));
#pragma unroll
        for (int i = 0; i < 2; i++) {
            int cc = tid + i * NTHR;           // 0..1023
            u32 d = SWZ((u32)cc * 16);
            CP16(st + ST_BH + d, bhs + cc * 16);
            CP16(st + ST_BL + d, bls + cc * 16);
        }
    };

    issue(0, 0); CP_COMMIT();
    issue(1, 1); CP_COMMIT();
    issue(2, 2); CP_COMMIT();

    int stg = 0;
    for (int k = 0; k < KK; k++) {
        CP_WAIT2();
        __syncthreads();

        const u32 st = tiles + stg * STAGE;
#pragma unroll
        for (int ks = 0; ks < 4; ks++) {
            u32 ah[2][4], al[2][4], bh[2][4], bl[2][4];
#pragma unroll
            for (int mf = 0; mf < 2; mf++) {
                u32 off = (a_row + mf * 16) * 128 + (u32)(ks * 32) + a_co * 16;
                u32 ad = st + SWZ(off);
                ldsm4(ah[mf], ad);
                ldsm4(al[mf], ad + TILEB);
            }
#pragma unroll
            for (int g = 0; g < 2; g++) {
                u32 off = (b_row + g * 16) * 128 + (u32)(ks * 32) + b_co * 16;
                u32 bd = st + ST_BH + SWZ(off);
                ldsm4(bh[g], bd);
                ldsm4(bl[g], bd + TILEB);
            }
            // main: ah . bh  (f32 accum, 8 independent)
#pragma unroll
            for (int mf = 0; mf < 2; mf++)
#pragma unroll
                for (int g = 0; g < 2; g++) {
                    mma_f32(accM[mf][2 * g],     ah[mf], &bh[g][0]);
                    mma_f32(accM[mf][2 * g + 1], ah[mf], &bh[g][2]);
                }
            // corrections: ah . bl  (f16 accum)
#pragma unroll
            for (int mf = 0; mf < 2; mf++)
#pragma unroll
                for (int g = 0; g < 2; g++) {
                    mma_f16(accC[mf][2 * g],     ah[mf], &bl[g][0]);
                    mma_f16(accC[mf][2 * g + 1], ah[mf], &bl[g][2]);
                }
            // corrections: al . bh  (f16 accum, same accumulators)
#pragma unroll
            for (int mf = 0; mf < 2; mf++)
#pragma unroll
                for (int g = 0; g < 2; g++) {
                    mma_f16(accC[mf][2 * g],     al[mf], &bh[g][0]);
                    mma_f16(accC[mf][2 * g + 1], al[mf], &bh[g][2]);
                }
        }
        __syncthreads();
        if (k + 3 < KK) issue(k + 3, stg);
        CP_COMMIT();
        stg = (stg == NSTAGE - 1) ? 0 : stg + 1;
    }

    // ---- epilogue: combine main + corrections, relu, coalesced stores ----
    float* sC = (float*)(smem + TILES_OFF);
#pragma unroll
    for (int mf = 0; mf < 2; mf++)
#pragma unroll
        for (int nf = 0; nf < 4; nf++) {
            __half2 c01 = *(__half2*)&accC[mf][nf][0];   // r=0,1
            __half2 c23 = *(__half2*)&accC[mf][nf][1];   // r=2,3
            float cf[4] = {__half2float(c01.x), __half2float(c01.y),
                           __half2float(c23.x), __half2float(c23.y)};
#pragma unroll
            for (int r = 0; r < 4; r++) {
                float v = accM[mf][nf][r] + cf[r];
                int m = wr * 32 + mf * 16 + (lid >> 2) + ((r >> 1) << 3);
                int n = wc * 32 + nf * 8 + ((lid & 3) << 1) + (r & 1);
                sC[n * 132 + m] = fmaxf(v, 0.f);
            }
        }
    __syncthreads();
#pragma unroll
    for (int it = 0; it < 8; it++) {
        int idx = it * NTHR + tid;
        int o = idx >> 5, hq = idx & 31;
        int h = hb + hq * 4;
        if (h < HH) {
            float4 v = *(const float4*)(sC + o * 132 + hq * 4);
            *(float4*)(out + (size_t)o * HH + h) = v;
        }
    }
}

// ---------------- launch ----------------
extern "C" void kernel_launch(void* const* d_in, const int* in_sizes, int n_in,
                              void* d_out, int out_size) {
    const float* x = (const float*)d_in[0];
    const void* neigh = d_in[1];
    const float* w = (const float*)d_in[2];
    float* out = (float*)d_out;

    cudaFuncSetAttribute(conv_mma, cudaFuncAttributeMaxDynamicSharedMemorySize, SMEM_BYTES);

    detect_dtype<<<1, 32>>>((const long long*)neigh);
    split_x<<<dim3((HH + 31) / 32, C_IN / 32), dim3(32, 8)>>>(x);
    split_w<<<(KK * C_OUT * C_IN + 255) / 256, 256>>>(w);
    conv_mma<<<NBLK, NTHR, SMEM_BYTES>>>(neigh, out);
}

// round 11
// speedup vs baseline: 3.6564x; 1.4980x over previous
#include <cuda_runtime.h>
#include <cuda_fp16.h>
#include <cstdint>

typedef unsigned int u32;
typedef unsigned long long u64;

#define C_IN   64
#define C_OUT  128
#define KK     27
#define HH     100000
#define TILE_H 128
#define NBLK   ((HH + TILE_H - 1) / TILE_H)
#define NTHR   512

// smem: 128B rows + SW128 XOR swizzle (conflict-free ldmatrix)
#define TILEB  16384               // 128 rows x 128 B
#define ST_A   0
#define ST_BH  TILEB
#define ST_BL  (2 * TILEB)
#define STAGE  (3 * TILEB)         // 49152
#define NSTAGE 3
#define TILES_OFF 14336            // after sIdx (13824 B)
#define SMEM_BYTES (TILES_OFF + NSTAGE * STAGE)   // 161792

#define SWZ(o) ((o) ^ (((o) >> 3) & 0x70))

// ---------------- device scratch ----------------
__device__ __half g_x[(size_t)HH * C_IN];    // [h][c] single fp16
__device__ __half g_wh[KK * C_OUT * C_IN];   // [k][o][c] fp16 hi
__device__ __half g_wl[KK * C_OUT * C_IN];   // [k][o][c] fp16 lo (residual)
__device__ int g_is64;

// ---------------- helpers ----------------
__device__ __forceinline__ u32 smem_u32(const void* p) {
    u32 a;
    asm("{ .reg .u64 t; cvta.to.shared.u64 t, %1; cvt.u32.u64 %0, t; }" : "=r"(a) : "l"(p));
    return a;
}
__device__ __forceinline__ void ldsm4(u32* r, u32 addr) {
    asm volatile("ldmatrix.sync.aligned.m8n8.x4.shared.b16 {%0,%1,%2,%3}, [%4];"
                 : "=r"(r[0]), "=r"(r[1]), "=r"(r[2]), "=r"(r[3]) : "r"(addr));
}
__device__ __forceinline__ void mma_f32(float* d, const u32* a, const u32* b) {
    asm volatile("mma.sync.aligned.m16n8k16.row.col.f32.f16.f16.f32 "
                 "{%0,%1,%2,%3}, {%4,%5,%6,%7}, {%8,%9}, {%0,%1,%2,%3};"
                 : "+f"(d[0]), "+f"(d[1]), "+f"(d[2]), "+f"(d[3])
                 : "r"(a[0]), "r"(a[1]), "r"(a[2]), "r"(a[3]), "r"(b[0]), "r"(b[1]));
}
#define CP16(dst, src) \
    asm volatile("cp.async.cg.shared.global [%0], [%1], 16;" ::"r"(dst), "l"(src) : "memory")
#define CP16Z(dst, src, sz) \
    asm volatile("cp.async.cg.shared.global [%0], [%1], 16, %2;" ::"r"(dst), "l"(src), "r"(sz) : "memory")
#define CP_COMMIT() asm volatile("cp.async.commit_group;" ::: "memory")
#define CP_WAIT2()  asm volatile("cp.async.wait_group 2;" ::: "memory")

// ---------------- prep kernels ----------------
__global__ void detect_dtype(const long long* __restrict__ n64) {
    if (threadIdx.x == 0 && blockIdx.x == 0) {
        int ok = 1;
        for (int i = 0; i < 256; i++) {
            long long v = n64[i];
            if (v < -(long long)HH || v >= (long long)HH) { ok = 0; break; }
        }
        g_is64 = ok;
    }
}

// x[c*HH + h] -> g_x[h*64 + c]  (transpose, single fp16)
__global__ void conv_x(const float* __restrict__ x) {
    __shared__ float tile[32][33];
    const int hb = blockIdx.x * 32, cb = blockIdx.y * 32;
    const int tx = threadIdx.x, ty = threadIdx.y;
#pragma unroll
    for (int i = 0; i < 32; i += 8) {
        int h = hb + tx;
        tile[ty + i][tx] = (h < HH) ? x[(size_t)(cb + ty + i) * HH + h] : 0.f;
    }
    __syncthreads();
#pragma unroll
    for (int i = 0; i < 32; i += 8) {
        int h = hb + ty + i, c = cb + tx;
        if (h < HH) g_x[(size_t)h * C_IN + c] = __float2half(tile[tx][ty + i]);
    }
}

// w[o*1728 + c*27 + k] -> g_wh/g_wl[k*8192 + o*64 + c]  (fp16 split)
__global__ void split_w(const float* __restrict__ w) {
    int idx = blockIdx.x * blockDim.x + threadIdx.x;
    if (idx >= KK * C_OUT * C_IN) return;
    int k = idx / (C_OUT * C_IN);
    int rem = idx % (C_OUT * C_IN);
    int o = rem / C_IN, c = rem % C_IN;
    float v = w[(size_t)o * (C_IN * KK) + c * KK + k];
    __half hi = __float2half(v);
    float r = v - __half2float(hi);
    g_wh[idx] = hi;
    g_wl[idx] = __float2half(r);
}

// ---------------- main kernel ----------------
__global__ __launch_bounds__(NTHR, 1)
void conv_mma(const void* __restrict__ neigh_raw, float* __restrict__ out) {
    extern __shared__ char smem[];
    const u32 sbase = smem_u32(smem);
    int* sIdx = (int*)smem;
    const u32 tiles = sbase + TILES_OFF;

    const int tid = threadIdx.x;
    const int lid = tid & 31, wid = tid >> 5;    // 16 warps
    const int wr = wid & 3, wc = wid >> 2;       // warp grid 4(h) x 4(o)
    const int hb = blockIdx.x * TILE_H;

    // ---- stage neighbor indices ----
    {
        const int is64 = g_is64;
        const long long* n64 = (const long long*)neigh_raw;
        const int* n32 = (const int*)neigh_raw;
        for (int j = tid; j < TILE_H * KK; j += NTHR) {
            int hl = j / KK;
            int n = -1;
            if (hb + hl < HH) {
                size_t gi = (size_t)(hb + hl) * KK + (j % KK);
                long long v = is64 ? n64[gi] : (long long)n32[gi];
                if (v >= 0 && v < HH) n = (int)v;
            }
            sIdx[j] = n;
        }
    }
    __syncthreads();

    // ---- per-thread load roles: A = 4 threads per row, 2 x 16B each ----
    const int ar   = tid >> 2;                 // 0..127
    const int jgrp = (tid & 3) * 2;            // 16B chunk pair index

    // ---- ldmatrix lane address components ----
    const u32 a_ro = (u32)(lid & 15);
    const u32 a_co = (u32)(lid >> 4);
    const u32 b_ro = (u32)((lid & 7) + ((lid >> 4) << 3));
    const u32 b_co = (u32)((lid >> 3) & 1);
    const u32 a_row = (u32)(wr * 32) + a_ro;
    const u32 b_row = (u32)(wc * 32) + b_ro;

    float accM[2][4][4];
#pragma unroll
    for (int mf = 0; mf < 2; mf++)
#pragma unroll
        for (int nf = 0; nf < 4; nf++)
#pragma unroll
            for (int r = 0; r < 4; r++) accM[mf][nf][r] = 0.f;

    // ---- async load issuer for tap k into stage stg ----
    auto issue = [&](int k, int stg) {
        const u32 st = tiles + stg * STAGE;
        // A: single fp16 gather row, this thread does 2 x 16B
        int n = sIdx[ar * KK + k];
        const char* src = (const char*)(g_x + (n < 0 ? 0 : (size_t)n * C_IN)) + jgrp * 16;
        u32 sz = (n < 0) ? 0u : 16u;
        u32 rowoff = (u32)ar * 128 + (u32)jgrp * 16;
        CP16Z(st + ST_A + SWZ(rowoff),      src,      sz);
        CP16Z(st + ST_A + SWZ(rowoff + 16), src + 16, sz);
        // B: weights hi+lo, 2 chunks each
        const char* bhs = (const char*)(g_wh + (size_t)k * (C_OUT * C_IN));
        const char* bls = (const char*)(g_wl + (size_t)k * (C_OUT * C_IN));
#pragma unroll
        for (int i = 0; i < 2; i++) {
            int cc = tid + i * NTHR;           // 0..1023
            u32 d = SWZ((u32)cc * 16);
            CP16(st + ST_BH + d, bhs + cc * 16);
            CP16(st + ST_BL + d, bls + cc * 16);
        }
    };

    issue(0, 0); CP_COMMIT();
    issue(1, 1); CP_COMMIT();
    issue(2, 2); CP_COMMIT();

    int stg = 0;
    for (int k = 0; k < KK; k++) {
        CP_WAIT2();
        __syncthreads();

        const u32 st = tiles + stg * STAGE;
#pragma unroll
        for (int ks = 0; ks < 4; ks++) {
            u32 a[2][4], bh[2][4], bl[2][4];
#pragma unroll
            for (int mf = 0; mf < 2; mf++) {
                u32 off = (a_row + mf * 16) * 128 + (u32)(ks * 32) + a_co * 16;
                ldsm4(a[mf], st + SWZ(off));
            }
#pragma unroll
            for (int g = 0; g < 2; g++) {
                u32 off = (b_row + g * 16) * 128 + (u32)(ks * 32) + b_co * 16;
                u32 bd = st + ST_BH + SWZ(off);
                ldsm4(bh[g], bd);
                ldsm4(bl[g], bd + (ST_BL - ST_BH));
            }
            // term 1: a . wh  (8 independent MMAs)
#pragma unroll
            for (int mf = 0; mf < 2; mf++)
#pragma unroll
                for (int g = 0; g < 2; g++) {
                    mma_f32(accM[mf][2 * g],     a[mf], &bh[g][0]);
                    mma_f32(accM[mf][2 * g + 1], a[mf], &bh[g][2]);
                }
            // term 2: a . wl  (8 independent MMAs)
#pragma unroll
            for (int mf = 0; mf < 2; mf++)
#pragma unroll
                for (int g = 0; g < 2; g++) {
                    mma_f32(accM[mf][2 * g],     a[mf], &bl[g][0]);
                    mma_f32(accM[mf][2 * g + 1], a[mf], &bl[g][2]);
                }
        }
        __syncthreads();
        if (k + 3 < KK) issue(k + 3, stg);
        CP_COMMIT();
        stg = (stg == NSTAGE - 1) ? 0 : stg + 1;
    }

    // ---- epilogue: relu, stage via smem (pitch 132), coalesced f4 stores ----
    float* sC = (float*)(smem + TILES_OFF);
#pragma unroll
    for (int mf = 0; mf < 2; mf++)
#pragma unroll
        for (int nf = 0; nf < 4; nf++)
#pragma unroll
            for (int r = 0; r < 4; r++) {
                int m = wr * 32 + mf * 16 + (lid >> 2) + ((r >> 1) << 3);
                int n = wc * 32 + nf * 8 + ((lid & 3) << 1) + (r & 1);
                sC[n * 132 + m] = fmaxf(accM[mf][nf][r], 0.f);
            }
    __syncthreads();
#pragma unroll
    for (int it = 0; it < 8; it++) {
        int idx = it * NTHR + tid;
        int o = idx >> 5, hq = idx & 31;
        int h = hb + hq * 4;
        if (h < HH) {
            float4 v = *(const float4*)(sC + o * 132 + hq * 4);
            *(float4*)(out + (size_t)o * HH + h) = v;
        }
    }
}

// ---------------- launch ----------------
extern "C" void kernel_launch(void* const* d_in, const int* in_sizes, int n_in,
                              void* d_out, int out_size) {
    const float* x = (const float*)d_in[0];
    const void* neigh = d_in[1];
    const float* w = (const float*)d_in[2];
    float* out = (float*)d_out;

    cudaFuncSetAttribute(conv_mma, cudaFuncAttributeMaxDynamicSharedMemorySize, SMEM_BYTES);

    detect_dtype<<<1, 32>>>((const long long*)neigh);
    conv_x<<<dim3((HH + 31) / 32, C_IN / 32), dim3(32, 8)>>>(x);
    split_w<<<(KK * C_OUT * C_IN + 255) / 256, 256>>>(w);
    conv_mma<<<NBLK, NTHR, SMEM_BYTES>>>(neigh, out);
}

// round 12
// speedup vs baseline: 3.8342x; 1.0486x over previous
#include <cuda_runtime.h>
#include <cuda_fp16.h>
#include <cstdint>

typedef unsigned int u32;
typedef unsigned long long u64;

#define C_IN   64
#define C_OUT  128
#define KK     27
#define HH     100000
#define TILE_H 128
#define NBLK   ((HH + TILE_H - 1) / TILE_H)
#define NTHR   512

// smem: 128B rows + SW128 XOR swizzle (conflict-free ldmatrix)
#define TILEB  16384               // 128 rows x 128 B
#define ST_A   0
#define ST_B   TILEB
#define STAGE  (2 * TILEB)         // 32768
#define NSTAGE 3
#define TILES_OFF 14336            // after sIdx (13824 B)
#define SMEM_BYTES (TILES_OFF + NSTAGE * STAGE)   // 112640

#define SWZ(o) ((o) ^ (((o) >> 3) & 0x70))

// ---------------- device scratch ----------------
__device__ __half g_x[(size_t)HH * C_IN];    // [h][c] fp16
__device__ __half g_w[KK * C_OUT * C_IN];    // [k][o][c] fp16
__device__ int g_is64;

// ---------------- helpers ----------------
__device__ __forceinline__ u32 smem_u32(const void* p) {
    u32 a;
    asm("{ .reg .u64 t; cvta.to.shared.u64 t, %1; cvt.u32.u64 %0, t; }" : "=r"(a) : "l"(p));
    return a;
}
__device__ __forceinline__ void ldsm4(u32* r, u32 addr) {
    asm volatile("ldmatrix.sync.aligned.m8n8.x4.shared.b16 {%0,%1,%2,%3}, [%4];"
                 : "=r"(r[0]), "=r"(r[1]), "=r"(r[2]), "=r"(r[3]) : "r"(addr));
}
__device__ __forceinline__ void mma_f32(float* d, const u32* a, const u32* b) {
    asm volatile("mma.sync.aligned.m16n8k16.row.col.f32.f16.f16.f32 "
                 "{%0,%1,%2,%3}, {%4,%5,%6,%7}, {%8,%9}, {%0,%1,%2,%3};"
                 : "+f"(d[0]), "+f"(d[1]), "+f"(d[2]), "+f"(d[3])
                 : "r"(a[0]), "r"(a[1]), "r"(a[2]), "r"(a[3]), "r"(b[0]), "r"(b[1]));
}
#define CP16(dst, src) \
    asm volatile("cp.async.cg.shared.global [%0], [%1], 16;" ::"r"(dst), "l"(src) : "memory")
#define CP16Z(dst, src, sz) \
    asm volatile("cp.async.cg.shared.global [%0], [%1], 16, %2;" ::"r"(dst), "l"(src), "r"(sz) : "memory")
#define CP_COMMIT() asm volatile("cp.async.commit_group;" ::: "memory")
#define CP_WAIT2()  asm volatile("cp.async.wait_group 2;" ::: "memory")

// ---------------- prep kernels ----------------
__global__ void detect_dtype(const long long* __restrict__ n64) {
    if (threadIdx.x == 0 && blockIdx.x == 0) {
        int ok = 1;
        for (int i = 0; i < 256; i++) {
            long long v = n64[i];
            if (v < -(long long)HH || v >= (long long)HH) { ok = 0; break; }
        }
        g_is64 = ok;
    }
}

// x[c*HH + h] -> g_x[h*64 + c]  (transpose, fp16)
__global__ void conv_x(const float* __restrict__ x) {
    __shared__ float tile[32][33];
    const int hb = blockIdx.x * 32, cb = blockIdx.y * 32;
    const int tx = threadIdx.x, ty = threadIdx.y;
#pragma unroll
    for (int i = 0; i < 32; i += 8) {
        int h = hb + tx;
        tile[ty + i][tx] = (h < HH) ? x[(size_t)(cb + ty + i) * HH + h] : 0.f;
    }
    __syncthreads();
#pragma unroll
    for (int i = 0; i < 32; i += 8) {
        int h = hb + ty + i, c = cb + tx;
        if (h < HH) g_x[(size_t)h * C_IN + c] = __float2half(tile[tx][ty + i]);
    }
}

// w[o*1728 + c*27 + k] -> g_w[k*8192 + o*64 + c]  (fp16)
__global__ void conv_w(const float* __restrict__ w) {
    int idx = blockIdx.x * blockDim.x + threadIdx.x;
    if (idx >= KK * C_OUT * C_IN) return;
    int k = idx / (C_OUT * C_IN);
    int rem = idx % (C_OUT * C_IN);
    int o = rem / C_IN, c = rem % C_IN;
    g_w[idx] = __float2half(w[(size_t)o * (C_IN * KK) + c * KK + k]);
}

// ---------------- main kernel ----------------
__global__ __launch_bounds__(NTHR, 1)
void conv_mma(const void* __restrict__ neigh_raw, float* __restrict__ out) {
    extern __shared__ char smem[];
    const u32 sbase = smem_u32(smem);
    int* sIdx = (int*)smem;
    const u32 tiles = sbase + TILES_OFF;

    const int tid = threadIdx.x;
    const int lid = tid & 31, wid = tid >> 5;    // 16 warps
    const int wr = wid & 3, wc = wid >> 2;       // warp grid 4(h) x 4(o)
    const int hb = blockIdx.x * TILE_H;

    // ---- stage neighbor indices ----
    {
        const int is64 = g_is64;
        const long long* n64 = (const long long*)neigh_raw;
        const int* n32 = (const int*)neigh_raw;
        for (int j = tid; j < TILE_H * KK; j += NTHR) {
            int hl = j / KK;
            int n = -1;
            if (hb + hl < HH) {
                size_t gi = (size_t)(hb + hl) * KK + (j % KK);
                long long v = is64 ? n64[gi] : (long long)n32[gi];
                if (v >= 0 && v < HH) n = (int)v;
            }
            sIdx[j] = n;
        }
    }
    __syncthreads();

    // ---- per-thread load roles: A = 4 threads per row, 2 x 16B each ----
    const int ar   = tid >> 2;                 // 0..127
    const int jgrp = (tid & 3) * 2;            // 16B chunk pair index

    // ---- ldmatrix lane address components ----
    const u32 a_ro = (u32)(lid & 15);
    const u32 a_co = (u32)(lid >> 4);
    const u32 b_ro = (u32)((lid & 7) + ((lid >> 4) << 3));
    const u32 b_co = (u32)((lid >> 3) & 1);
    const u32 a_row = (u32)(wr * 32) + a_ro;
    const u32 b_row = (u32)(wc * 32) + b_ro;

    float accM[2][4][4];
#pragma unroll
    for (int mf = 0; mf < 2; mf++)
#pragma unroll
        for (int nf = 0; nf < 4; nf++)
#pragma unroll
            for (int r = 0; r < 4; r++) accM[mf][nf][r] = 0.f;

    // ---- async load issuer for tap k into stage stg ----
    auto issue = [&](int k, int stg) {
        const u32 st = tiles + stg * STAGE;
        // A: fp16 gather row, this thread does 2 x 16B
        int n = sIdx[ar * KK + k];
        const char* src = (const char*)(g_x + (n < 0 ? 0 : (size_t)n * C_IN)) + jgrp * 16;
        u32 sz = (n < 0) ? 0u : 16u;
        u32 rowoff = (u32)ar * 128 + (u32)jgrp * 16;
        CP16Z(st + ST_A + SWZ(rowoff),      src,      sz);
        CP16Z(st + ST_A + SWZ(rowoff + 16), src + 16, sz);
        // B: weights, 1024 chunks, 2 per thread
        const char* bs = (const char*)(g_w + (size_t)k * (C_OUT * C_IN));
#pragma unroll
        for (int i = 0; i < 2; i++) {
            int cc = tid + i * NTHR;
            CP16(st + ST_B + SWZ((u32)cc * 16), bs + cc * 16);
        }
    };

    issue(0, 0); CP_COMMIT();
    issue(1, 1); CP_COMMIT();
    issue(2, 2); CP_COMMIT();

    int stg = 0;
    for (int k = 0; k < KK; k++) {
        CP_WAIT2();
        __syncthreads();

        const u32 st = tiles + stg * STAGE;
#pragma unroll
        for (int ks = 0; ks < 4; ks++) {
            u32 a[2][4], b[2][4];
#pragma unroll
            for (int mf = 0; mf < 2; mf++) {
                u32 off = (a_row + mf * 16) * 128 + (u32)(ks * 32) + a_co * 16;
                ldsm4(a[mf], st + SWZ(off));
            }
#pragma unroll
            for (int g = 0; g < 2; g++) {
                u32 off = (b_row + g * 16) * 128 + (u32)(ks * 32) + b_co * 16;
                ldsm4(b[g], st + ST_B + SWZ(off));
            }
#pragma unroll
            for (int mf = 0; mf < 2; mf++)
#pragma unroll
                for (int g = 0; g < 2; g++) {
                    mma_f32(accM[mf][2 * g],     a[mf], &b[g][0]);
                    mma_f32(accM[mf][2 * g + 1], a[mf], &b[g][2]);
                }
        }
        __syncthreads();
        if (k + 3 < KK) issue(k + 3, stg);
        CP_COMMIT();
        stg = (stg == NSTAGE - 1) ? 0 : stg + 1;
    }

    // ---- epilogue: relu, stage via smem (pitch 132), coalesced f4 stores ----
    float* sC = (float*)(smem + TILES_OFF);
#pragma unroll
    for (int mf = 0; mf < 2; mf++)
#pragma unroll
        for (int nf = 0; nf < 4; nf++)
#pragma unroll
            for (int r = 0; r < 4; r++) {
                int m = wr * 32 + mf * 16 + (lid >> 2) + ((r >> 1) << 3);
                int n = wc * 32 + nf * 8 + ((lid & 3) << 1) + (r & 1);
                sC[n * 132 + m] = fmaxf(accM[mf][nf][r], 0.f);
            }
    __syncthreads();
#pragma unroll
    for (int it = 0; it < 8; it++) {
        int idx = it * NTHR + tid;
        int o = idx >> 5, hq = idx & 31;
        int h = hb + hq * 4;
        if (h < HH) {
            float4 v = *(const float4*)(sC + o * 132 + hq * 4);
            *(float4*)(out + (size_t)o * HH + h) = v;
        }
    }
}

// ---------------- launch ----------------
extern "C" void kernel_launch(void* const* d_in, const int* in_sizes, int n_in,
                              void* d_out, int out_size) {
    const float* x = (const float*)d_in[0];
    const void* neigh = d_in[1];
    const float* w = (const float*)d_in[2];
    float* out = (float*)d_out;

    cudaFuncSetAttribute(conv_mma, cudaFuncAttributeMaxDynamicSharedMemorySize, SMEM_BYTES);

    detect_dtype<<<1, 32>>>((const long long*)neigh);
    conv_x<<<dim3((HH + 31) / 32, C_IN / 32), dim3(32, 8)>>>(x);
    conv_w<<<(KK * C_OUT * C_IN + 255) / 256, 256>>>(w);
    conv_mma<<<NBLK, NTHR, SMEM_BYTES>>>(neigh, out);
}

// round 13
// speedup vs baseline: 5.5231x; 1.4405x over previous
#include <cuda_runtime.h>
#include <cuda_fp16.h>
#include <cstdint>

typedef unsigned int u32;
typedef unsigned long long u64;

#define C_IN   64
#define C_OUT  128
#define KK     27
#define KKP    28                  // padded (tap 27 = zeros)
#define NP     14                  // double-tap pairs
#define HH     100000
#define TILE_H 128
#define NBLK   ((HH + TILE_H - 1) / TILE_H)
#define NTHR   512

// smem: 128B rows + SW128 XOR swizzle
// stage (64KB): A0 +0, A1 +16K, B0 +32K, B1 +48K
#define TILEB  16384
#define STAGE  (4 * TILEB)
#define NSTAGE 3
#define TILES_OFF 14336            // sIdx = 128*28*4 = 14336 B exactly
#define SMEM_BYTES (TILES_OFF + NSTAGE * STAGE)   // 210944

#define SWZ(o) ((o) ^ (((o) >> 3) & 0x70))

// ---------------- device scratch ----------------
__device__ __half g_x[(size_t)HH * C_IN];      // [h][c] fp16
__device__ __half g_w[KKP * C_OUT * C_IN];     // [k][o][c] fp16, tap 27 zeroed
__device__ int g_is64;

// ---------------- helpers ----------------
__device__ __forceinline__ u32 smem_u32(const void* p) {
    u32 a;
    asm("{ .reg .u64 t; cvta.to.shared.u64 t, %1; cvt.u32.u64 %0, t; }" : "=r"(a) : "l"(p));
    return a;
}
__device__ __forceinline__ void ldsm4(u32* r, u32 addr) {
    asm volatile("ldmatrix.sync.aligned.m8n8.x4.shared.b16 {%0,%1,%2,%3}, [%4];"
                 : "=r"(r[0]), "=r"(r[1]), "=r"(r[2]), "=r"(r[3]) : "r"(addr));
}
__device__ __forceinline__ void mma_f32(float* d, const u32* a, const u32* b) {
    asm volatile("mma.sync.aligned.m16n8k16.row.col.f32.f16.f16.f32 "
                 "{%0,%1,%2,%3}, {%4,%5,%6,%7}, {%8,%9}, {%0,%1,%2,%3};"
                 : "+f"(d[0]), "+f"(d[1]), "+f"(d[2]), "+f"(d[3])
                 : "r"(a[0]), "r"(a[1]), "r"(a[2]), "r"(a[3]), "r"(b[0]), "r"(b[1]));
}
#define CP16(dst, src) \
    asm volatile("cp.async.cg.shared.global [%0], [%1], 16;" ::"r"(dst), "l"(src) : "memory")
#define CP16Z(dst, src, sz) \
    asm volatile("cp.async.cg.shared.global [%0], [%1], 16, %2;" ::"r"(dst), "l"(src), "r"(sz) : "memory")
#define CP_COMMIT() asm volatile("cp.async.commit_group;" ::: "memory")
#define CP_WAIT1()  asm volatile("cp.async.wait_group 1;" ::: "memory")

// ---------------- prep kernels ----------------
__global__ void detect_dtype(const long long* __restrict__ n64) {
    if (threadIdx.x == 0 && blockIdx.x == 0) {
        int ok = 1;
        for (int i = 0; i < 256; i++) {
            long long v = n64[i];
            if (v < -(long long)HH || v >= (long long)HH) { ok = 0; break; }
        }
        g_is64 = ok;
    }
}

// x[c*HH + h] -> g_x[h*64 + c]
__global__ void conv_x(const float* __restrict__ x) {
    __shared__ float tile[32][33];
    const int hb = blockIdx.x * 32, cb = blockIdx.y * 32;
    const int tx = threadIdx.x, ty = threadIdx.y;
#pragma unroll
    for (int i = 0; i < 32; i += 8) {
        int h = hb + tx;
        tile[ty + i][tx] = (h < HH) ? x[(size_t)(cb + ty + i) * HH + h] : 0.f;
    }
    __syncthreads();
#pragma unroll
    for (int i = 0; i < 32; i += 8) {
        int h = hb + ty + i, c = cb + tx;
        if (h < HH) g_x[(size_t)h * C_IN + c] = __float2half(tile[tx][ty + i]);
    }
}

// w[o*1728 + c*27 + k] -> g_w[k*8192 + o*64 + c]; tap 27 zeroed
__global__ void conv_w(const float* __restrict__ w) {
    int idx = blockIdx.x * blockDim.x + threadIdx.x;
    if (idx >= KKP * C_OUT * C_IN) return;
    int k = idx / (C_OUT * C_IN);
    int rem = idx % (C_OUT * C_IN);
    int o = rem / C_IN, c = rem % C_IN;
    g_w[idx] = (k < KK) ? __float2half(w[(size_t)o * (C_IN * KK) + c * KK + k])
                        : __float2half(0.f);
}

// ---------------- main kernel ----------------
__global__ __launch_bounds__(NTHR, 1)
void conv_mma(const void* __restrict__ neigh_raw, float* __restrict__ out) {
    extern __shared__ char smem[];
    const u32 sbase = smem_u32(smem);
    int* sIdx = (int*)smem;                       // [128][28]
    const u32 tiles = sbase + TILES_OFF;

    const int tid = threadIdx.x;
    const int lid = tid & 31, wid = tid >> 5;     // 16 warps
    const int wr = wid & 3, wc = wid >> 2;        // 4(h) x 4(o)
    const int hb = blockIdx.x * TILE_H;

    // ---- stage neighbor indices (padded tap 27 -> -1) ----
    {
        const int is64 = g_is64;
        const long long* n64 = (const long long*)neigh_raw;
        const int* n32 = (const int*)neigh_raw;
        for (int j = tid; j < TILE_H * KKP; j += NTHR) {
            int hl = j / KKP, kk = j % KKP;
            int n = -1;
            if (kk < KK && hb + hl < HH) {
                size_t gi = (size_t)(hb + hl) * KK + kk;
                long long v = is64 ? n64[gi] : (long long)n32[gi];
                if (v >= 0 && v < HH) n = (int)v;
            }
            sIdx[j] = n;
        }
    }
    __syncthreads();

    // ---- per-thread load roles ----
    const int ar   = tid >> 2;                 // gather row 0..127
    const int jgrp = (tid & 3) * 2;            // 16B chunk pair

    // ---- ldmatrix address precompute ----
    const u32 a_ro = (u32)(lid & 15);
    const u32 a_co = (u32)(lid >> 4);
    const u32 b_ro = (u32)((lid & 7) + ((lid >> 4) << 3));
    const u32 b_co = (u32)((lid >> 3) & 1);
    const u32 a_row = (u32)(wr * 32) + a_ro;
    const u32 b_row = (u32)(wc * 32) + b_ro;
    const u32 axor = (a_row & 7) * 16;
    const u32 bxor = (b_row & 7) * 16;
    const u32 arow0 = a_row * 128, arow1 = (a_row + 16) * 128;
    const u32 brow0 = b_row * 128, brow1 = (b_row + 16) * 128;
    u32 koffA[4], koffB[4];
#pragma unroll
    for (int ks = 0; ks < 4; ks++) {
        koffA[ks] = ((u32)(ks * 32) + a_co * 16) ^ axor;
        koffB[ks] = ((u32)(ks * 32) + b_co * 16) ^ bxor;
    }

    float acc[2][4][4];
#pragma unroll
    for (int mf = 0; mf < 2; mf++)
#pragma unroll
        for (int nf = 0; nf < 4; nf++)
#pragma unroll
            for (int r = 0; r < 4; r++) acc[mf][nf][r] = 0.f;

    // ---- issue one PAIR of taps (2p, 2p+1) into stage s ----
    auto issue = [&](int p, int s) {
        const u32 st = tiles + s * STAGE;
        const int k0 = 2 * p;
        const u32 rowoff = (u32)ar * 128 + (u32)jgrp * 16;
#pragma unroll
        for (int t = 0; t < 2; t++) {
            int n = sIdx[ar * KKP + k0 + t];
            const char* src = (const char*)(g_x + (n < 0 ? 0 : (size_t)n * C_IN)) + jgrp * 16;
            u32 sz = (n < 0) ? 0u : 16u;
            const u32 dst = st + t * TILEB;
            CP16Z(dst + SWZ(rowoff),      src,      sz);
            CP16Z(dst + SWZ(rowoff + 16), src + 16, sz);
        }
        // B: two weight taps, 2 chunks per thread each
#pragma unroll
        for (int t = 0; t < 2; t++) {
            const char* bs = (const char*)(g_w + (size_t)(k0 + t) * (C_OUT * C_IN));
            const u32 dst = st + (2 + t) * TILEB;
#pragma unroll
            for (int i = 0; i < 2; i++) {
                int cc = tid + i * NTHR;
                CP16(dst + SWZ((u32)cc * 16), bs + cc * 16);
            }
        }
    };

    issue(0, 0); CP_COMMIT();
    issue(1, 1); CP_COMMIT();

    for (int p = 0; p < NP; p++) {
        const int s = p % NSTAGE;
        CP_WAIT1();
        __syncthreads();                        // all warps done with pair p-1

        if (p + 2 < NP) issue(p + 2, (p + 2) % NSTAGE);
        CP_COMMIT();

        const u32 st = tiles + s * STAGE;
#pragma unroll
        for (int t = 0; t < 2; t++) {
            const u32 stA = st + t * TILEB;
            const u32 stB = st + (2 + t) * TILEB;
#pragma unroll
            for (int ks = 0; ks < 4; ks++) {
                u32 a[2][4], b[2][4];
                ldsm4(a[0], stA + arow0 + koffA[ks]);
                ldsm4(a[1], stA + arow1 + koffA[ks]);
                ldsm4(b[0], stB + brow0 + koffB[ks]);
                ldsm4(b[1], stB + brow1 + koffB[ks]);
#pragma unroll
                for (int mf = 0; mf < 2; mf++)
#pragma unroll
                    for (int g = 0; g < 2; g++) {
                        mma_f32(acc[mf][2 * g],     a[mf], &b[g][0]);
                        mma_f32(acc[mf][2 * g + 1], a[mf], &b[g][2]);
                    }
            }
        }
    }

    __syncthreads();   // all warps done with final pair; sC aliases tile smem
    // ---- epilogue: relu, stage via smem (pitch 132), coalesced f4 stores ----
    float* sC = (float*)(smem + TILES_OFF);
#pragma unroll
    for (int mf = 0; mf < 2; mf++)
#pragma unroll
        for (int nf = 0; nf < 4; nf++)
#pragma unroll
            for (int r = 0; r < 4; r++) {
                int m = wr * 32 + mf * 16 + (lid >> 2) + ((r >> 1) << 3);
                int n = wc * 32 + nf * 8 + ((lid & 3) << 1) + (r & 1);
                sC[n * 132 + m] = fmaxf(acc[mf][nf][r], 0.f);
            }
    __syncthreads();
#pragma unroll
    for (int it = 0; it < 8; it++) {
        int idx = it * NTHR + tid;
        int o = idx >> 5, hq = idx & 31;
        int h = hb + hq * 4;
        if (h < HH) {
            float4 v = *(const float4*)(sC + o * 132 + hq * 4);
            *(float4*)(out + (size_t)o * HH + h) = v;
        }
    }
}

// ---------------- launch ----------------
extern "C" void kernel_launch(void* const* d_in, const int* in_sizes, int n_in,
                              void* d_out, int out_size) {
    const float* x = (const float*)d_in[0];
    const void* neigh = d_in[1];
    const float* w = (const float*)d_in[2];
    float* out = (float*)d_out;

    cudaFuncSetAttribute(conv_mma, cudaFuncAttributeMaxDynamicSharedMemorySize, SMEM_BYTES);

    detect_dtype<<<1, 32>>>((const long long*)neigh);
    conv_x<<<dim3((HH + 31) / 32, C_IN / 32), dim3(32, 8)>>>(x);
    conv_w<<<(KKP * C_OUT * C_IN + 255) / 256, 256>>>(w);
    conv_mma<<<NBLK, NTHR, SMEM_BYTES>>>(neigh, out);
}

// round 14
// speedup vs baseline: 6.7898x; 1.2294x over previous
#include <cuda_runtime.h>
#include <cuda_fp16.h>
#include <cstdint>

typedef unsigned int u32;
typedef unsigned long long u64;

#define C_IN   64
#define C_OUT  128
#define KK     27
#define KKP    28                  // padded (tap 27 = zeros)
#define NP     14                  // double-tap pairs
#define HH     100000
#define TILE_H 64
#define NBLK   ((HH + TILE_H - 1) / TILE_H)
#define NTHR   256

// smem: 128B rows + SW128 XOR swizzle
// pair stage (48KB): A0 +0 (8K), A1 +8K, B0 +16K (16K), B1 +32K
#define A_TILE 8192
#define B_TILE 16384
#define STAGE  49152
#define NSTAGE 2
#define TILES_OFF 7168             // sIdx = 64*28*4 = 7168 B exactly
#define SMEM_BYTES (TILES_OFF + NSTAGE * STAGE)   // 105472 -> 2 CTAs/SM

#define SWZ(o) ((o) ^ (((o) >> 3) & 0x70))

// ---------------- device scratch ----------------
__device__ __half g_x[(size_t)HH * C_IN];      // [h][c] fp16
__device__ __half g_w[KKP * C_OUT * C_IN];     // [k][o][c] fp16, tap 27 zeroed
__device__ int g_is64;

// ---------------- helpers ----------------
__device__ __forceinline__ u32 smem_u32(const void* p) {
    u32 a;
    asm("{ .reg .u64 t; cvta.to.shared.u64 t, %1; cvt.u32.u64 %0, t; }" : "=r"(a) : "l"(p));
    return a;
}
__device__ __forceinline__ void ldsm4(u32* r, u32 addr) {
    asm volatile("ldmatrix.sync.aligned.m8n8.x4.shared.b16 {%0,%1,%2,%3}, [%4];"
                 : "=r"(r[0]), "=r"(r[1]), "=r"(r[2]), "=r"(r[3]) : "r"(addr));
}
__device__ __forceinline__ void mma_f32(float* d, const u32* a, const u32* b) {
    asm volatile("mma.sync.aligned.m16n8k16.row.col.f32.f16.f16.f32 "
                 "{%0,%1,%2,%3}, {%4,%5,%6,%7}, {%8,%9}, {%0,%1,%2,%3};"
                 : "+f"(d[0]), "+f"(d[1]), "+f"(d[2]), "+f"(d[3])
                 : "r"(a[0]), "r"(a[1]), "r"(a[2]), "r"(a[3]), "r"(b[0]), "r"(b[1]));
}
#define CP16(dst, src) \
    asm volatile("cp.async.cg.shared.global [%0], [%1], 16;" ::"r"(dst), "l"(src) : "memory")
#define CP16Z(dst, src, sz) \
    asm volatile("cp.async.cg.shared.global [%0], [%1], 16, %2;" ::"r"(dst), "l"(src), "r"(sz) : "memory")
#define CP_COMMIT()  asm volatile("cp.async.commit_group;" ::: "memory")
#define CP_WAITALL() asm volatile("cp.async.wait_group 0;" ::: "memory")

// ---------------- prep kernels ----------------
__global__ void detect_dtype(const long long* __restrict__ n64) {
    if (threadIdx.x == 0 && blockIdx.x == 0) {
        int ok = 1;
        for (int i = 0; i < 256; i++) {
            long long v = n64[i];
            if (v < -(long long)HH || v >= (long long)HH) { ok = 0; break; }
        }
        g_is64 = ok;
    }
}

// x[c*HH + h] -> g_x[h*64 + c]
__global__ void conv_x(const float* __restrict__ x) {
    __shared__ float tile[32][33];
    const int hb = blockIdx.x * 32, cb = blockIdx.y * 32;
    const int tx = threadIdx.x, ty = threadIdx.y;
#pragma unroll
    for (int i = 0; i < 32; i += 8) {
        int h = hb + tx;
        tile[ty + i][tx] = (h < HH) ? x[(size_t)(cb + ty + i) * HH + h] : 0.f;
    }
    __syncthreads();
#pragma unroll
    for (int i = 0; i < 32; i += 8) {
        int h = hb + ty + i, c = cb + tx;
        if (h < HH) g_x[(size_t)h * C_IN + c] = __float2half(tile[tx][ty + i]);
    }
}

// w[o*1728 + c*27 + k] -> g_w[k*8192 + o*64 + c]; tap 27 zeroed
__global__ void conv_w(const float* __restrict__ w) {
    int idx = blockIdx.x * blockDim.x + threadIdx.x;
    if (idx >= KKP * C_OUT * C_IN) return;
    int k = idx / (C_OUT * C_IN);
    int rem = idx % (C_OUT * C_IN);
    int o = rem / C_IN, c = rem % C_IN;
    g_w[idx] = (k < KK) ? __float2half(w[(size_t)o * (C_IN * KK) + c * KK + k])
                        : __float2half(0.f);
}

// ---------------- main kernel ----------------
__global__ __launch_bounds__(NTHR, 2)
void conv_mma(const void* __restrict__ neigh_raw, float* __restrict__ out) {
    extern __shared__ char smem[];
    const u32 sbase = smem_u32(smem);
    int* sIdx = (int*)smem;                       // [64][28]
    const u32 tiles = sbase + TILES_OFF;

    const int tid = threadIdx.x;
    const int lid = tid & 31, wid = tid >> 5;     // 8 warps
    const int wr = wid & 1, wc = wid >> 1;        // 2(h) x 4(o)
    const int hb = blockIdx.x * TILE_H;

    // ---- stage neighbor indices (padded tap 27 -> -1) ----
    {
        const int is64 = g_is64;
        const long long* n64 = (const long long*)neigh_raw;
        const int* n32 = (const int*)neigh_raw;
        for (int j = tid; j < TILE_H * KKP; j += NTHR) {
            int hl = j / KKP, kk = j % KKP;
            int n = -1;
            if (kk < KK && hb + hl < HH) {
                size_t gi = (size_t)(hb + hl) * KK + kk;
                long long v = is64 ? n64[gi] : (long long)n32[gi];
                if (v >= 0 && v < HH) n = (int)v;
            }
            sIdx[j] = n;
        }
    }
    __syncthreads();

    // ---- per-thread load roles ----
    const int ar   = tid >> 2;                 // gather row 0..63
    const int jgrp = (tid & 3) * 2;            // 16B chunk pair

    // ---- ldmatrix address precompute ----
    const u32 a_ro = (u32)(lid & 15);
    const u32 a_co = (u32)(lid >> 4);
    const u32 b_ro = (u32)((lid & 7) + ((lid >> 4) << 3));
    const u32 b_co = (u32)((lid >> 3) & 1);
    const u32 a_row = (u32)(wr * 32) + a_ro;
    const u32 b_row = (u32)(wc * 32) + b_ro;
    const u32 axor = (a_row & 7) * 16;
    const u32 bxor = (b_row & 7) * 16;
    const u32 arow0 = a_row * 128, arow1 = (a_row + 16) * 128;
    const u32 brow0 = b_row * 128, brow1 = (b_row + 16) * 128;
    u32 koffA[4], koffB[4];
#pragma unroll
    for (int ks = 0; ks < 4; ks++) {
        koffA[ks] = ((u32)(ks * 32) + a_co * 16) ^ axor;
        koffB[ks] = ((u32)(ks * 32) + b_co * 16) ^ bxor;
    }

    float acc[2][4][4];
#pragma unroll
    for (int mf = 0; mf < 2; mf++)
#pragma unroll
        for (int nf = 0; nf < 4; nf++)
#pragma unroll
            for (int r = 0; r < 4; r++) acc[mf][nf][r] = 0.f;

    // ---- issue one PAIR of taps (2p, 2p+1) into stage s ----
    auto issue = [&](int p, int s) {
        const u32 st = tiles + s * STAGE;
        const int k0 = 2 * p;
        const u32 rowoff = (u32)ar * 128 + (u32)jgrp * 16;
        // A: 2 taps x 64 rows x 128B; this thread does 2 x 16B per tap
#pragma unroll
        for (int t = 0; t < 2; t++) {
            int n = sIdx[ar * KKP + k0 + t];
            const char* src = (const char*)(g_x + (n < 0 ? 0 : (size_t)n * C_IN)) + jgrp * 16;
            u32 sz = (n < 0) ? 0u : 16u;
            const u32 dst = st + t * A_TILE;
            CP16Z(dst + SWZ(rowoff),      src,      sz);
            CP16Z(dst + SWZ(rowoff + 16), src + 16, sz);
        }
        // B: 2 weight taps, 16KB each, 4 chunks per thread per tap
#pragma unroll
        for (int t = 0; t < 2; t++) {
            const char* bs = (const char*)(g_w + (size_t)(k0 + t) * (C_OUT * C_IN));
            const u32 dst = st + 2 * A_TILE + t * B_TILE;
#pragma unroll
            for (int i = 0; i < 4; i++) {
                int cc = tid + i * NTHR;
                CP16(dst + SWZ((u32)cc * 16), bs + cc * 16);
            }
        }
    };

    issue(0, 0); CP_COMMIT();

    for (int p = 0; p < NP; p++) {
        const int s = p & 1;
        CP_WAITALL();                           // pair p's data landed
        __syncthreads();                        // all warps done reading pair p-1

        if (p + 1 < NP) { issue(p + 1, s ^ 1); CP_COMMIT(); }

        const u32 st = tiles + s * STAGE;
#pragma unroll
        for (int t = 0; t < 2; t++) {
            const u32 stA = st + t * A_TILE;
            const u32 stB = st + 2 * A_TILE + t * B_TILE;
#pragma unroll
            for (int ks = 0; ks < 4; ks++) {
                u32 a[2][4], b[2][4];
                ldsm4(a[0], stA + arow0 + koffA[ks]);
                ldsm4(a[1], stA + arow1 + koffA[ks]);
                ldsm4(b[0], stB + brow0 + koffB[ks]);
                ldsm4(b[1], stB + brow1 + koffB[ks]);
#pragma unroll
                for (int mf = 0; mf < 2; mf++)
#pragma unroll
                    for (int g = 0; g < 2; g++) {
                        mma_f32(acc[mf][2 * g],     a[mf], &b[g][0]);
                        mma_f32(acc[mf][2 * g + 1], a[mf], &b[g][2]);
                    }
            }
        }
    }

    __syncthreads();   // all warps done; sC aliases tile smem
    // ---- epilogue: relu, stage via smem [o][h] pitch 68, coalesced stores ----
    float* sC = (float*)(smem + TILES_OFF);
#pragma unroll
    for (int mf = 0; mf < 2; mf++)
#pragma unroll
        for (int nf = 0; nf < 4; nf++)
#pragma unroll
            for (int r = 0; r < 4; r++) {
                int m = wr * 32 + mf * 16 + (lid >> 2) + ((r >> 1) << 3);
                int n = wc * 32 + nf * 8 + ((lid & 3) << 1) + (r & 1);
                sC[n * 68 + m] = fmaxf(acc[mf][nf][r], 0.f);
            }
    __syncthreads();
#pragma unroll
    for (int it = 0; it < 8; it++) {
        int idx = it * NTHR + tid;               // 2048 float4
        int o = idx >> 4, hq = idx & 15;
        int h = hb + hq * 4;
        if (h < HH) {
            float4 v = *(const float4*)(sC + o * 68 + hq * 4);
            *(float4*)(out + (size_t)o * HH + h) = v;
        }
    }
}

// ---------------- launch ----------------
extern "C" void kernel_launch(void* const* d_in, const int* in_sizes, int n_in,
                              void* d_out, int out_size) {
    const float* x = (const float*)d_in[0];
    const void* neigh = d_in[1];
    const float* w = (const float*)d_in[2];
    float* out = (float*)d_out;

    cudaFuncSetAttribute(conv_mma, cudaFuncAttributeMaxDynamicSharedMemorySize, SMEM_BYTES);

    detect_dtype<<<1, 32>>>((const long long*)neigh);
    conv_x<<<dim3((HH + 31) / 32, C_IN / 32), dim3(32, 8)>>>(x);
    conv_w<<<(KKP * C_OUT * C_IN + 255) / 256, 256>>>(w);
    conv_mma<<<NBLK, NTHR, SMEM_BYTES>>>(neigh, out);
}